// round 12
// baseline (speedup 1.0000x reference)
#include <cuda_runtime.h>
#include <cuda_bf16.h>
#include <cstddef>
#include <cstdint>

#define B_   2
#define S_   2048
#define E_   2048
#define H_   32
#define HKV_ 8
#define D_   64
#define G_   4
#define KVW  (HKV_ * D_)    // 512
#define NQKV (E_ + 2 * KVW) // 3072

// ---------------------------------------------------------------------------
// Scratch (zero-init .bss, no allocation)
// ---------------------------------------------------------------------------
__device__ __nv_bfloat16 g_x_hi[(size_t)B_ * S_ * E_];
__device__ __nv_bfloat16 g_x_lo[(size_t)B_ * S_ * E_];
__device__ __nv_bfloat16 g_Wqkv_hi[(size_t)NQKV * E_];  // [Wq;Wk;Wv] rows
__device__ __nv_bfloat16 g_Wqkv_lo[(size_t)NQKV * E_];
__device__ __nv_bfloat16 g_Wo_hi[(size_t)E_ * E_];
__device__ __nv_bfloat16 g_Wo_lo[(size_t)E_ * E_];

__device__ __nv_bfloat16 g_Qbh[(size_t)B_ * S_ * E_];
__device__ __nv_bfloat16 g_Qbl[(size_t)B_ * S_ * E_];
__device__ __nv_bfloat16 g_Kbh[(size_t)B_ * S_ * KVW];
__device__ __nv_bfloat16 g_Kbl[(size_t)B_ * S_ * KVW];
__device__ __nv_bfloat16 g_Vbh[(size_t)B_ * S_ * KVW];
__device__ __nv_bfloat16 g_Vbl[(size_t)B_ * S_ * KVW];

__device__ __nv_bfloat16 g_attn_hi[(size_t)B_ * S_ * E_];
__device__ __nv_bfloat16 g_attn_lo[(size_t)B_ * S_ * E_];

// ---------------------------------------------------------------------------
// helpers
// ---------------------------------------------------------------------------
__device__ __forceinline__ unsigned smaddr(const void* p)
{
    return (unsigned)__cvta_generic_to_shared(p);
}
__device__ __forceinline__ unsigned packbf(float lo, float hi)
{
    unsigned r;
    asm("cvt.rn.bf16x2.f32 %0, %1, %2;" : "=r"(r) : "f"(hi), "f"(lo));
    return r;
}
__device__ __forceinline__ void split2(float x, float y, unsigned& hi, unsigned& lo)
{
    hi = packbf(x, y);
    float xh = __uint_as_float(hi << 16);
    float yh = __uint_as_float(hi & 0xffff0000u);
    lo = packbf(x - xh, y - yh);
}
__device__ __forceinline__ void mma16816(float* c, const unsigned* a, const unsigned* b)
{
    asm volatile(
        "mma.sync.aligned.m16n8k16.row.col.f32.bf16.bf16.f32 "
        "{%0,%1,%2,%3}, {%4,%5,%6,%7}, {%8,%9}, {%0,%1,%2,%3};\n"
        : "+f"(c[0]), "+f"(c[1]), "+f"(c[2]), "+f"(c[3])
        : "r"(a[0]), "r"(a[1]), "r"(a[2]), "r"(a[3]), "r"(b[0]), "r"(b[1]));
}
__device__ __forceinline__ void mma16816_b2(float* c, const unsigned* a,
                                            unsigned b0, unsigned b1)
{
    asm volatile(
        "mma.sync.aligned.m16n8k16.row.col.f32.bf16.bf16.f32 "
        "{%0,%1,%2,%3}, {%4,%5,%6,%7}, {%8,%9}, {%0,%1,%2,%3};\n"
        : "+f"(c[0]), "+f"(c[1]), "+f"(c[2]), "+f"(c[3])
        : "r"(a[0]), "r"(a[1]), "r"(a[2]), "r"(a[3]), "r"(b0), "r"(b1));
}
__device__ __forceinline__ void ldmx2t(unsigned& r0, unsigned& r1, const __nv_bfloat16* p)
{
    unsigned addr = smaddr(p);
    asm volatile("ldmatrix.sync.aligned.m8n8.x2.trans.shared.b16 {%0,%1}, [%2];"
                 : "=r"(r0), "=r"(r1) : "r"(addr));
}
__device__ __forceinline__ void ldmx4(unsigned* r, const __nv_bfloat16* p)
{
    unsigned addr = smaddr(p);
    asm volatile("ldmatrix.sync.aligned.m8n8.x4.shared.b16 {%0,%1,%2,%3}, [%4];"
                 : "=r"(r[0]), "=r"(r[1]), "=r"(r[2]), "=r"(r[3]) : "r"(addr));
}
__device__ __forceinline__ void cpasync16(void* smem, const void* gmem)
{
    unsigned s = smaddr(smem);
    asm volatile("cp.async.cg.shared.global [%0], [%1], 16;" :: "r"(s), "l"(gmem));
}

// ---------------------------------------------------------------------------
// fp32 -> (hi, lo) bf16 split (contiguous)
// ---------------------------------------------------------------------------
__global__ void split_kernel(const float* __restrict__ src,
                             __nv_bfloat16* __restrict__ hi,
                             __nv_bfloat16* __restrict__ lo, int n)
{
    int i = blockIdx.x * blockDim.x + threadIdx.x;
    if (i >= n) return;
    float a = src[i];
    __nv_bfloat16 h = __float2bfloat16(a);
    hi[i] = h;
    lo[i] = __float2bfloat16(a - __bfloat162float(h));
}

// ---------------------------------------------------------------------------
// Split-bf16 NT GEMM: BM=128, BN=256, BK=32, 3-stage cp.async, ldmatrix.
// 8 warps (2 M x 4 N), warp tile 64x64. smem stride 40 halves (conflict-free).
// mode 0: fp32 store to C.
// mode 1: fused QKV epilogue -> rope+scale+split direct to g_Qb*/g_Kb*/g_Vb*.
// ---------------------------------------------------------------------------
#define GST 40
#define ASZ (128 * GST)
#define BSZ (256 * GST)
#define STSZ (2 * ASZ + 2 * BSZ)
#define GEMM_SMEM (3 * STSZ * 2)

__global__ __launch_bounds__(256, 1) void gemm_split_nt3_kernel(
    const __nv_bfloat16* __restrict__ Ahi, const __nv_bfloat16* __restrict__ Alo,
    const __nv_bfloat16* __restrict__ Bhi, const __nv_bfloat16* __restrict__ Blo,
    float* __restrict__ C, int M, int N, int K, int mode,
    const float* __restrict__ cosT, const float* __restrict__ sinT)
{
    extern __shared__ __nv_bfloat16 smg[];

    int tid  = threadIdx.x;
    int lane = tid & 31;
    int wid  = tid >> 5;
    int wm = wid & 1;
    int wn = wid >> 1;
    int g  = lane >> 2;
    int t2 = (lane & 3) * 2;
    int l16 = lane & 15;
    int lc8 = (lane >> 4) * 8;

    int m0 = blockIdx.y * 128;
    int n0 = blockIdx.x * 256;

    float acc[4][8][4];
#pragma unroll
    for (int i = 0; i < 4; i++)
#pragma unroll
        for (int j = 0; j < 8; j++)
#pragma unroll
            for (int r = 0; r < 4; r++) acc[i][j][r] = 0.0f;

    auto stage_load = [&](int k0, int s) {
        __nv_bfloat16* base = smg + s * STSZ;
#pragma unroll
        for (int c = tid; c < 512; c += 256) {
            int row = c >> 2, ch = (c & 3) * 8;
            size_t ga = (size_t)(m0 + row) * K + k0 + ch;
            int so = row * GST + ch;
            cpasync16(base + so,       Ahi + ga);
            cpasync16(base + ASZ + so, Alo + ga);
        }
#pragma unroll
        for (int c = tid; c < 1024; c += 256) {
            int row = c >> 2, ch = (c & 3) * 8;
            size_t gb = (size_t)(n0 + row) * K + k0 + ch;
            int so = row * GST + ch;
            cpasync16(base + 2 * ASZ + so,       Bhi + gb);
            cpasync16(base + 2 * ASZ + BSZ + so, Blo + gb);
        }
    };

    int T = K / 32;
    stage_load(0, 0);
    asm volatile("cp.async.commit_group;" ::: "memory");
    stage_load(32, 1);
    asm volatile("cp.async.commit_group;" ::: "memory");

    for (int it = 0; it < T; it++) {
        asm volatile("cp.async.wait_group 1;" ::: "memory");
        __syncthreads();

        int st = it % 3;
        __nv_bfloat16* base = smg + st * STSZ;
        __nv_bfloat16* sAh = base;
        __nv_bfloat16* sAl = base + ASZ;
        __nv_bfloat16* sBh = base + 2 * ASZ;
        __nv_bfloat16* sBl = base + 2 * ASZ + BSZ;

#pragma unroll
        for (int ks = 0; ks < 32; ks += 16) {
            int col = ks + lc8;
            unsigned ah[4][4], al[4][4];
#pragma unroll
            for (int mi = 0; mi < 4; mi++) {
                int ar = wm * 64 + mi * 16 + l16;
                ldmx4(ah[mi], sAh + ar * GST + col);
                ldmx4(al[mi], sAl + ar * GST + col);
            }
#pragma unroll
            for (int nq = 0; nq < 4; nq++) {
                unsigned bh4[4], bl4[4];
                int br = wn * 64 + nq * 16 + l16;
                ldmx4(bh4, sBh + br * GST + col);
                ldmx4(bl4, sBl + br * GST + col);
#pragma unroll
                for (int mi = 0; mi < 4; mi++) {
                    mma16816_b2(acc[mi][2 * nq],     ah[mi], bh4[0], bh4[2]);
                    mma16816_b2(acc[mi][2 * nq],     ah[mi], bl4[0], bl4[2]);
                    mma16816_b2(acc[mi][2 * nq],     al[mi], bh4[0], bh4[2]);
                    mma16816_b2(acc[mi][2 * nq + 1], ah[mi], bh4[1], bh4[3]);
                    mma16816_b2(acc[mi][2 * nq + 1], ah[mi], bl4[1], bl4[3]);
                    mma16816_b2(acc[mi][2 * nq + 1], al[mi], bh4[1], bh4[3]);
                }
            }
        }
        __syncthreads();
        if (it + 2 < T) stage_load((it + 2) * 32, (it + 2) % 3);
        asm volatile("cp.async.commit_group;" ::: "memory");
    }

    if (mode == 0) {
#pragma unroll
        for (int mi = 0; mi < 4; mi++) {
#pragma unroll
            for (int ni = 0; ni < 8; ni++) {
                int row = m0 + wm * 64 + mi * 16 + g;
                int col = n0 + wn * 64 + ni * 8 + t2;
                *(float2*)&C[(size_t)row * N + col] =
                    make_float2(acc[mi][ni][0], acc[mi][ni][1]);
                *(float2*)&C[(size_t)(row + 8) * N + col] =
                    make_float2(acc[mi][ni][2], acc[mi][ni][3]);
            }
        }
        return;
    }

    // mode 1: fused QKV epilogue. Warp tile (64 cols) = exactly one head.
    int colbase = n0 + wn * 64;
    int region = (colbase < E_) ? 0 : (colbase < E_ + KVW) ? 1 : 2;

#pragma unroll
    for (int mi = 0; mi < 4; mi++) {
#pragma unroll
        for (int rr = 0; rr < 2; rr++) {
            int row = m0 + wm * 64 + mi * 16 + g + rr * 8;
            int s = row & (S_ - 1);
            if (region == 2) {
                // V: plain split
                size_t ob = (size_t)row * KVW + (colbase - E_ - KVW);
#pragma unroll
                for (int ni = 0; ni < 8; ni++) {
                    unsigned hi, lo;
                    split2(acc[mi][ni][rr * 2], acc[mi][ni][rr * 2 + 1], hi, lo);
                    *(unsigned*)&g_Vbh[ob + ni * 8 + t2] = hi;
                    *(unsigned*)&g_Vbl[ob + ni * 8 + t2] = lo;
                }
            } else {
                float scale = (region == 0) ? 0.125f : 1.0f;
                __nv_bfloat16* outh = (region == 0) ? g_Qbh : g_Kbh;
                __nv_bfloat16* outl = (region == 0) ? g_Qbl : g_Kbl;
                size_t ob = (region == 0)
                    ? (size_t)row * E_ + colbase
                    : (size_t)row * KVW + (colbase - E_);
#pragma unroll
                for (int ni = 0; ni < 4; ni++) {
                    int d = ni * 8 + t2;             // 0..30
                    float a0  = acc[mi][ni][rr * 2];
                    float a0b = acc[mi][ni][rr * 2 + 1];
                    float a1  = acc[mi][ni + 4][rr * 2];
                    float a1b = acc[mi][ni + 4][rr * 2 + 1];
                    float2 cl = *(const float2*)&cosT[s * D_ + d];
                    float2 sl = *(const float2*)&sinT[s * D_ + d];
                    float2 ch = *(const float2*)&cosT[s * D_ + d + 32];
                    float2 sh = *(const float2*)&sinT[s * D_ + d + 32];
                    float r0  = (a0  * cl.x - a1  * sl.x) * scale;
                    float r0b = (a0b * cl.y - a1b * sl.y) * scale;
                    float r1  = (a1  * ch.x + a0  * sh.x) * scale;
                    float r1b = (a1b * ch.y + a0b * sh.y) * scale;
                    unsigned hi, lo;
                    split2(r0, r0b, hi, lo);
                    *(unsigned*)&outh[ob + d] = hi;
                    *(unsigned*)&outl[ob + d] = lo;
                    split2(r1, r1b, hi, lo);
                    *(unsigned*)&outh[ob + d + 32] = hi;
                    *(unsigned*)&outl[ob + d + 32] = lo;
                }
            }
        }
    }
}

// ---------------------------------------------------------------------------
// Tensor-core flash attention, split-bf16, Br=128, Bc=64, D=64.
// Q fragments hoisted to registers; K/V via 2-stage cp.async pipeline.
// ---------------------------------------------------------------------------
#define AST 72
#define KVST (4 * 64 * AST)                  // halves per K/V stage
#define ATTN_SMEM ((2 * 128 * AST + 2 * KVST) * 2)   // bytes = 110592

__global__ __launch_bounds__(256) void attn_mma_kernel()
{
    extern __shared__ __nv_bfloat16 smb[];
    __nv_bfloat16* sQh = smb;
    __nv_bfloat16* sQl = smb + 128 * AST;
    __nv_bfloat16* kvbase = smb + 256 * AST;  // 2 stages of [Kh, Kl, Vh, Vl]

    int tid  = threadIdx.x;
    int lane = tid & 31;
    int wid  = tid >> 5;
    int g    = lane >> 2;
    int t2   = (lane & 3) * 2;
    int l16  = lane & 15;
    int lc8  = (lane >> 4) * 8;

    int qt = blockIdx.x, h = blockIdx.y, b = blockIdx.z;
    int kvh = h >> 2;
    int s0 = qt * 128;

    const __nv_bfloat16* Qhg = g_Qbh + ((size_t)(b * S_ + s0)) * E_ + h * D_;
    const __nv_bfloat16* Qlg = g_Qbl + ((size_t)(b * S_ + s0)) * E_ + h * D_;
    const __nv_bfloat16* Khg = g_Kbh + (size_t)b * S_ * KVW + kvh * D_;
    const __nv_bfloat16* Klg = g_Kbl + (size_t)b * S_ * KVW + kvh * D_;
    const __nv_bfloat16* Vhg = g_Vbh + (size_t)b * S_ * KVW + kvh * D_;
    const __nv_bfloat16* Vlg = g_Vbl + (size_t)b * S_ * KVW + kvh * D_;

    // Q tile to smem (once)
    for (int c = tid; c < 1024; c += 256) {
        int r = c >> 3, col = (c & 7) * 8;
        *(uint4*)&sQh[r * AST + col] = *(const uint4*)&Qhg[(size_t)r * E_ + col];
        *(uint4*)&sQl[r * AST + col] = *(const uint4*)&Qlg[(size_t)r * E_ + col];
    }

    auto kv_load = [&](int tile, int s) {
        __nv_bfloat16* base = kvbase + s * KVST;
        int t0 = tile * 64;
#pragma unroll
        for (int c = tid; c < 512; c += 256) {
            int r = c >> 3, ch = (c & 7) * 8;
            size_t ga = (size_t)(t0 + r) * KVW + ch;
            int so = r * AST + ch;
            cpasync16(base + so,                Khg + ga);
            cpasync16(base + 64 * AST + so,     Klg + ga);
            cpasync16(base + 2 * 64 * AST + so, Vhg + ga);
            cpasync16(base + 3 * 64 * AST + so, Vlg + ga);
        }
    };

    kv_load(0, 0);
    asm volatile("cp.async.commit_group;" ::: "memory");
    __syncthreads();   // Q smem ready for ldmatrix

    // Hoist Q fragments (reused over all key tiles)
    int wr = wid * 16;
    unsigned qfh[4][4], qfl[4][4];
#pragma unroll
    for (int kt = 0; kt < 4; kt++) {
        int col = kt * 16 + lc8;
        ldmx4(qfh[kt], sQh + (wr + l16) * AST + col);
        ldmx4(qfl[kt], sQl + (wr + l16) * AST + col);
    }

    float m0r = -1e30f, m1r = -1e30f, l0r = 0.0f, l1r = 0.0f;
    float O[8][4];
#pragma unroll
    for (int nt = 0; nt < 8; nt++)
#pragma unroll
        for (int r = 0; r < 4; r++) O[nt][r] = 0.0f;

    const int T = S_ / 64;
    for (int kt0 = 0; kt0 < T; kt0++) {
        if (kt0 + 1 < T) {
            kv_load(kt0 + 1, (kt0 + 1) & 1);
            asm volatile("cp.async.commit_group;" ::: "memory");
            asm volatile("cp.async.wait_group 1;" ::: "memory");
        } else {
            asm volatile("cp.async.wait_group 0;" ::: "memory");
        }
        __syncthreads();

        __nv_bfloat16* base = kvbase + (kt0 & 1) * KVST;
        __nv_bfloat16* sKh = base;
        __nv_bfloat16* sKl = base + 64 * AST;
        __nv_bfloat16* sVh = base + 2 * 64 * AST;
        __nv_bfloat16* sVl = base + 3 * 64 * AST;

        float acc[8][4];
#pragma unroll
        for (int nt = 0; nt < 8; nt++)
#pragma unroll
            for (int r = 0; r < 4; r++) acc[nt][r] = 0.0f;

#pragma unroll
        for (int kt = 0; kt < 4; kt++) {
            int col = kt * 16 + lc8;
#pragma unroll
            for (int nq = 0; nq < 4; nq++) {
                unsigned bh4[4], bl4[4];
                ldmx4(bh4, sKh + (nq * 16 + l16) * AST + col);
                ldmx4(bl4, sKl + (nq * 16 + l16) * AST + col);
                mma16816_b2(acc[2 * nq],     qfh[kt], bh4[0], bh4[2]);
                mma16816_b2(acc[2 * nq],     qfh[kt], bl4[0], bl4[2]);
                mma16816_b2(acc[2 * nq],     qfl[kt], bh4[0], bh4[2]);
                mma16816_b2(acc[2 * nq + 1], qfh[kt], bh4[1], bh4[3]);
                mma16816_b2(acc[2 * nq + 1], qfh[kt], bl4[1], bl4[3]);
                mma16816_b2(acc[2 * nq + 1], qfl[kt], bh4[1], bh4[3]);
            }
        }

        float mx0 = -1e30f, mx1 = -1e30f;
#pragma unroll
        for (int nt = 0; nt < 8; nt++) {
            mx0 = fmaxf(mx0, fmaxf(acc[nt][0], acc[nt][1]));
            mx1 = fmaxf(mx1, fmaxf(acc[nt][2], acc[nt][3]));
        }
        mx0 = fmaxf(mx0, __shfl_xor_sync(0xffffffffu, mx0, 1));
        mx0 = fmaxf(mx0, __shfl_xor_sync(0xffffffffu, mx0, 2));
        mx1 = fmaxf(mx1, __shfl_xor_sync(0xffffffffu, mx1, 1));
        mx1 = fmaxf(mx1, __shfl_xor_sync(0xffffffffu, mx1, 2));
        float nm0 = fmaxf(m0r, mx0), nm1 = fmaxf(m1r, mx1);
        float corr0 = __expf(m0r - nm0), corr1 = __expf(m1r - nm1);
        m0r = nm0; m1r = nm1;

        float sum0 = 0.0f, sum1 = 0.0f;
#pragma unroll
        for (int nt = 0; nt < 8; nt++) {
            acc[nt][0] = __expf(acc[nt][0] - nm0); sum0 += acc[nt][0];
            acc[nt][1] = __expf(acc[nt][1] - nm0); sum0 += acc[nt][1];
            acc[nt][2] = __expf(acc[nt][2] - nm1); sum1 += acc[nt][2];
            acc[nt][3] = __expf(acc[nt][3] - nm1); sum1 += acc[nt][3];
        }
        sum0 += __shfl_xor_sync(0xffffffffu, sum0, 1);
        sum0 += __shfl_xor_sync(0xffffffffu, sum0, 2);
        sum1 += __shfl_xor_sync(0xffffffffu, sum1, 1);
        sum1 += __shfl_xor_sync(0xffffffffu, sum1, 2);
        l0r = l0r * corr0 + sum0;
        l1r = l1r * corr1 + sum1;
#pragma unroll
        for (int nt = 0; nt < 8; nt++) {
            O[nt][0] *= corr0; O[nt][1] *= corr0;
            O[nt][2] *= corr1; O[nt][3] *= corr1;
        }

#pragma unroll
        for (int kt = 0; kt < 4; kt++) {
            unsigned ph[4], pl[4];
            split2(acc[2 * kt][0],     acc[2 * kt][1],     ph[0], pl[0]);
            split2(acc[2 * kt][2],     acc[2 * kt][3],     ph[1], pl[1]);
            split2(acc[2 * kt + 1][0], acc[2 * kt + 1][1], ph[2], pl[2]);
            split2(acc[2 * kt + 1][2], acc[2 * kt + 1][3], ph[3], pl[3]);
            const __nv_bfloat16* vh_base = sVh + (kt * 16 + l16) * AST;
            const __nv_bfloat16* vl_base = sVl + (kt * 16 + l16) * AST;
#pragma unroll
            for (int nt = 0; nt < 8; nt++) {
                unsigned bh[2], bl[2];
                ldmx2t(bh[0], bh[1], vh_base + nt * 8);
                ldmx2t(bl[0], bl[1], vl_base + nt * 8);
                mma16816(O[nt], ph, bh);
                mma16816(O[nt], ph, bl);
                mma16816(O[nt], pl, bh);
            }
        }
        __syncthreads();
    }

    float inv0 = 1.0f / l0r, inv1 = 1.0f / l1r;
    size_t row0 = (size_t)(b * S_ + s0 + wr + g) * E_ + h * D_;
    size_t row1 = (size_t)(b * S_ + s0 + wr + g + 8) * E_ + h * D_;
#pragma unroll
    for (int nt = 0; nt < 8; nt++) {
        unsigned hi, lo;
        split2(O[nt][0] * inv0, O[nt][1] * inv0, hi, lo);
        *(unsigned*)&g_attn_hi[row0 + nt * 8 + t2] = hi;
        *(unsigned*)&g_attn_lo[row0 + nt * 8 + t2] = lo;
        split2(O[nt][2] * inv1, O[nt][3] * inv1, hi, lo);
        *(unsigned*)&g_attn_hi[row1 + nt * 8 + t2] = hi;
        *(unsigned*)&g_attn_lo[row1 + nt * 8 + t2] = lo;
    }
}

// ---------------------------------------------------------------------------
// Launch
// ---------------------------------------------------------------------------
extern "C" void kernel_launch(void* const* d_in, const int* in_sizes, int n_in,
                              void* d_out, int out_size)
{
    const float* x    = (const float*)d_in[0];
    const float* cosT = (const float*)d_in[1];
    const float* sinT = (const float*)d_in[2];
    const float* Wq   = (const float*)d_in[3];
    const float* Wk   = (const float*)d_in[4];
    const float* Wv   = (const float*)d_in[5];
    const float* Wo   = (const float*)d_in[6];
    float* out = (float*)d_out;

    __nv_bfloat16 *xh, *xl, *wh, *wl, *oh, *ol, *ah, *al;
    cudaGetSymbolAddress((void**)&xh, g_x_hi);    cudaGetSymbolAddress((void**)&xl, g_x_lo);
    cudaGetSymbolAddress((void**)&wh, g_Wqkv_hi); cudaGetSymbolAddress((void**)&wl, g_Wqkv_lo);
    cudaGetSymbolAddress((void**)&oh, g_Wo_hi);   cudaGetSymbolAddress((void**)&ol, g_Wo_lo);
    cudaGetSymbolAddress((void**)&ah, g_attn_hi); cudaGetSymbolAddress((void**)&al, g_attn_lo);

    const int M = B_ * S_;   // 4096

    cudaFuncSetAttribute(gemm_split_nt3_kernel,
                         cudaFuncAttributeMaxDynamicSharedMemorySize, GEMM_SMEM);
    cudaFuncSetAttribute(attn_mma_kernel,
                         cudaFuncAttributeMaxDynamicSharedMemorySize, ATTN_SMEM);

    // Split conversions: x + weights (Wq/Wk/Wv fused rows, Wo)
    {
        int nx = M * E_;
        split_kernel<<<(nx + 255) / 256, 256>>>(x, xh, xl, nx);
        int nq = E_ * E_;
        int nk = KVW * E_;
        split_kernel<<<(nq + 255) / 256, 256>>>(Wq, wh, wl, nq);
        split_kernel<<<(nk + 255) / 256, 256>>>(Wk, wh + (size_t)E_ * E_,
                                                wl + (size_t)E_ * E_, nk);
        split_kernel<<<(nk + 255) / 256, 256>>>(Wv, wh + (size_t)(E_ + KVW) * E_,
                                                wl + (size_t)(E_ + KVW) * E_, nk);
        split_kernel<<<(nq + 255) / 256, 256>>>(Wo, oh, ol, nq);
    }

    // Fused QKV projection with rope+scale+split epilogue (mode 1)
    gemm_split_nt3_kernel<<<dim3(NQKV / 256, M / 128), 256, GEMM_SMEM>>>(
        xh, xl, wh, wl, nullptr, M, NQKV, E_, 1, cosT, sinT);

    // Attention
    attn_mma_kernel<<<dim3(S_ / 128, H_, B_), 256, ATTN_SMEM>>>();

    // Output projection -> d_out (mode 0)
    gemm_split_nt3_kernel<<<dim3(E_ / 256, M / 128), 256, GEMM_SMEM>>>(
        ah, al, oh, ol, out, M, E_, E_, 0, nullptr, nullptr);
}

// round 14
// speedup vs baseline: 1.0572x; 1.0572x over previous
#include <cuda_runtime.h>
#include <cuda_bf16.h>
#include <cstddef>
#include <cstdint>

#define B_   2
#define S_   2048
#define E_   2048
#define H_   32
#define HKV_ 8
#define D_   64
#define G_   4
#define KVW  (HKV_ * D_)    // 512
#define NQKV (E_ + 2 * KVW) // 3072

// ---------------------------------------------------------------------------
// Scratch (zero-init .bss, no allocation)
// ---------------------------------------------------------------------------
__device__ __nv_bfloat16 g_x_hi[(size_t)B_ * S_ * E_];
__device__ __nv_bfloat16 g_x_lo[(size_t)B_ * S_ * E_];
__device__ __nv_bfloat16 g_Wqkv_hi[(size_t)NQKV * E_];  // [Wq;Wk;Wv] rows
__device__ __nv_bfloat16 g_Wqkv_lo[(size_t)NQKV * E_];
__device__ __nv_bfloat16 g_Wo_hi[(size_t)E_ * E_];
__device__ __nv_bfloat16 g_Wo_lo[(size_t)E_ * E_];

__device__ __nv_bfloat16 g_Qbh[(size_t)B_ * S_ * E_];
__device__ __nv_bfloat16 g_Qbl[(size_t)B_ * S_ * E_];
__device__ __nv_bfloat16 g_Kbh[(size_t)B_ * S_ * KVW];
__device__ __nv_bfloat16 g_Kbl[(size_t)B_ * S_ * KVW];
__device__ __nv_bfloat16 g_Vbh[(size_t)B_ * S_ * KVW];
__device__ __nv_bfloat16 g_Vbl[(size_t)B_ * S_ * KVW];

__device__ __nv_bfloat16 g_attn_hi[(size_t)B_ * S_ * E_];
__device__ __nv_bfloat16 g_attn_lo[(size_t)B_ * S_ * E_];

// ---------------------------------------------------------------------------
// helpers
// ---------------------------------------------------------------------------
__device__ __forceinline__ unsigned smaddr(const void* p)
{
    return (unsigned)__cvta_generic_to_shared(p);
}
__device__ __forceinline__ unsigned packbf(float lo, float hi)
{
    unsigned r;
    asm("cvt.rn.bf16x2.f32 %0, %1, %2;" : "=r"(r) : "f"(hi), "f"(lo));
    return r;
}
__device__ __forceinline__ void split2(float x, float y, unsigned& hi, unsigned& lo)
{
    hi = packbf(x, y);
    float xh = __uint_as_float(hi << 16);
    float yh = __uint_as_float(hi & 0xffff0000u);
    lo = packbf(x - xh, y - yh);
}
__device__ __forceinline__ void mma16816(float* c, const unsigned* a, const unsigned* b)
{
    asm volatile(
        "mma.sync.aligned.m16n8k16.row.col.f32.bf16.bf16.f32 "
        "{%0,%1,%2,%3}, {%4,%5,%6,%7}, {%8,%9}, {%0,%1,%2,%3};\n"
        : "+f"(c[0]), "+f"(c[1]), "+f"(c[2]), "+f"(c[3])
        : "r"(a[0]), "r"(a[1]), "r"(a[2]), "r"(a[3]), "r"(b[0]), "r"(b[1]));
}
__device__ __forceinline__ void mma16816_b2(float* c, const unsigned* a,
                                            unsigned b0, unsigned b1)
{
    asm volatile(
        "mma.sync.aligned.m16n8k16.row.col.f32.bf16.bf16.f32 "
        "{%0,%1,%2,%3}, {%4,%5,%6,%7}, {%8,%9}, {%0,%1,%2,%3};\n"
        : "+f"(c[0]), "+f"(c[1]), "+f"(c[2]), "+f"(c[3])
        : "r"(a[0]), "r"(a[1]), "r"(a[2]), "r"(a[3]), "r"(b0), "r"(b1));
}
__device__ __forceinline__ void ldmx2t(unsigned& r0, unsigned& r1, const __nv_bfloat16* p)
{
    unsigned addr = smaddr(p);
    asm volatile("ldmatrix.sync.aligned.m8n8.x2.trans.shared.b16 {%0,%1}, [%2];"
                 : "=r"(r0), "=r"(r1) : "r"(addr));
}
__device__ __forceinline__ void ldmx4(unsigned* r, const __nv_bfloat16* p)
{
    unsigned addr = smaddr(p);
    asm volatile("ldmatrix.sync.aligned.m8n8.x4.shared.b16 {%0,%1,%2,%3}, [%4];"
                 : "=r"(r[0]), "=r"(r[1]), "=r"(r[2]), "=r"(r[3]) : "r"(addr));
}
__device__ __forceinline__ void cpasync16(void* smem, const void* gmem)
{
    unsigned s = smaddr(smem);
    asm volatile("cp.async.cg.shared.global [%0], [%1], 16;" :: "r"(s), "l"(gmem));
}

// ---------------------------------------------------------------------------
// fp32 -> (hi, lo) bf16 split (contiguous)
// ---------------------------------------------------------------------------
__global__ void split_kernel(const float* __restrict__ src,
                             __nv_bfloat16* __restrict__ hi,
                             __nv_bfloat16* __restrict__ lo, int n)
{
    int i = blockIdx.x * blockDim.x + threadIdx.x;
    if (i >= n) return;
    float a = src[i];
    __nv_bfloat16 h = __float2bfloat16(a);
    hi[i] = h;
    lo[i] = __float2bfloat16(a - __bfloat162float(h));
}

// ---------------------------------------------------------------------------
// Split-bf16 NT GEMM: BM=128, BN=256, BK=32, 3-stage cp.async, ldmatrix.
// 8 warps (2 M x 4 N), warp tile 64x64. smem stride 40 halves (conflict-free).
// MODE 0: fp32 store to C (identical to R10 code path).
// MODE 1: fused QKV epilogue -> rope+scale+split direct to g_Qb*/g_Kb*/g_Vb*.
// ---------------------------------------------------------------------------
#define GST 40
#define ASZ (128 * GST)
#define BSZ (256 * GST)
#define STSZ (2 * ASZ + 2 * BSZ)
#define GEMM_SMEM (3 * STSZ * 2)

template <int MODE>
__global__ __launch_bounds__(256, 1) void gemm_split_nt3_kernel(
    const __nv_bfloat16* __restrict__ Ahi, const __nv_bfloat16* __restrict__ Alo,
    const __nv_bfloat16* __restrict__ Bhi, const __nv_bfloat16* __restrict__ Blo,
    float* __restrict__ C, int M, int N, int K,
    const float* __restrict__ cosT, const float* __restrict__ sinT)
{
    extern __shared__ __nv_bfloat16 smg[];

    int tid  = threadIdx.x;
    int lane = tid & 31;
    int wid  = tid >> 5;
    int wm = wid & 1;
    int wn = wid >> 1;
    int g  = lane >> 2;
    int t2 = (lane & 3) * 2;
    int l16 = lane & 15;
    int lc8 = (lane >> 4) * 8;

    int m0 = blockIdx.y * 128;
    int n0 = blockIdx.x * 256;

    float acc[4][8][4];
#pragma unroll
    for (int i = 0; i < 4; i++)
#pragma unroll
        for (int j = 0; j < 8; j++)
#pragma unroll
            for (int r = 0; r < 4; r++) acc[i][j][r] = 0.0f;

    auto stage_load = [&](int k0, int s) {
        __nv_bfloat16* base = smg + s * STSZ;
#pragma unroll
        for (int c = tid; c < 512; c += 256) {
            int row = c >> 2, ch = (c & 3) * 8;
            size_t ga = (size_t)(m0 + row) * K + k0 + ch;
            int so = row * GST + ch;
            cpasync16(base + so,       Ahi + ga);
            cpasync16(base + ASZ + so, Alo + ga);
        }
#pragma unroll
        for (int c = tid; c < 1024; c += 256) {
            int row = c >> 2, ch = (c & 3) * 8;
            size_t gb = (size_t)(n0 + row) * K + k0 + ch;
            int so = row * GST + ch;
            cpasync16(base + 2 * ASZ + so,       Bhi + gb);
            cpasync16(base + 2 * ASZ + BSZ + so, Blo + gb);
        }
    };

    int T = K / 32;
    stage_load(0, 0);
    asm volatile("cp.async.commit_group;" ::: "memory");
    stage_load(32, 1);
    asm volatile("cp.async.commit_group;" ::: "memory");

    for (int it = 0; it < T; it++) {
        asm volatile("cp.async.wait_group 1;" ::: "memory");
        __syncthreads();

        int st = it % 3;
        __nv_bfloat16* base = smg + st * STSZ;
        __nv_bfloat16* sAh = base;
        __nv_bfloat16* sAl = base + ASZ;
        __nv_bfloat16* sBh = base + 2 * ASZ;
        __nv_bfloat16* sBl = base + 2 * ASZ + BSZ;

#pragma unroll
        for (int ks = 0; ks < 32; ks += 16) {
            int col = ks + lc8;
            unsigned ah[4][4], al[4][4];
#pragma unroll
            for (int mi = 0; mi < 4; mi++) {
                int ar = wm * 64 + mi * 16 + l16;
                ldmx4(ah[mi], sAh + ar * GST + col);
                ldmx4(al[mi], sAl + ar * GST + col);
            }
#pragma unroll
            for (int nq = 0; nq < 4; nq++) {
                unsigned bh4[4], bl4[4];
                int br = wn * 64 + nq * 16 + l16;
                ldmx4(bh4, sBh + br * GST + col);
                ldmx4(bl4, sBl + br * GST + col);
#pragma unroll
                for (int mi = 0; mi < 4; mi++) {
                    mma16816_b2(acc[mi][2 * nq],     ah[mi], bh4[0], bh4[2]);
                    mma16816_b2(acc[mi][2 * nq],     ah[mi], bl4[0], bl4[2]);
                    mma16816_b2(acc[mi][2 * nq],     al[mi], bh4[0], bh4[2]);
                    mma16816_b2(acc[mi][2 * nq + 1], ah[mi], bh4[1], bh4[3]);
                    mma16816_b2(acc[mi][2 * nq + 1], ah[mi], bl4[1], bl4[3]);
                    mma16816_b2(acc[mi][2 * nq + 1], al[mi], bh4[1], bh4[3]);
                }
            }
        }
        __syncthreads();
        if (it + 2 < T) stage_load((it + 2) * 32, (it + 2) % 3);
        asm volatile("cp.async.commit_group;" ::: "memory");
    }

    if (MODE == 0) {
#pragma unroll
        for (int mi = 0; mi < 4; mi++) {
#pragma unroll
            for (int ni = 0; ni < 8; ni++) {
                int row = m0 + wm * 64 + mi * 16 + g;
                int col = n0 + wn * 64 + ni * 8 + t2;
                *(float2*)&C[(size_t)row * N + col] =
                    make_float2(acc[mi][ni][0], acc[mi][ni][1]);
                *(float2*)&C[(size_t)(row + 8) * N + col] =
                    make_float2(acc[mi][ni][2], acc[mi][ni][3]);
            }
        }
        return;
    }

    // MODE 1: fused QKV epilogue. Warp tile (64 cols) = exactly one head.
    int colbase = n0 + wn * 64;
    int region = (colbase < E_) ? 0 : (colbase < E_ + KVW) ? 1 : 2;

#pragma unroll
    for (int mi = 0; mi < 4; mi++) {
#pragma unroll
        for (int rr = 0; rr < 2; rr++) {
            int row = m0 + wm * 64 + mi * 16 + g + rr * 8;
            int s = row & (S_ - 1);
            if (region == 2) {
                // V: plain split
                size_t ob = (size_t)row * KVW + (colbase - E_ - KVW);
#pragma unroll
                for (int ni = 0; ni < 8; ni++) {
                    unsigned hi, lo;
                    split2(acc[mi][ni][rr * 2], acc[mi][ni][rr * 2 + 1], hi, lo);
                    *(unsigned*)&g_Vbh[ob + ni * 8 + t2] = hi;
                    *(unsigned*)&g_Vbl[ob + ni * 8 + t2] = lo;
                }
            } else {
                float scale = (region == 0) ? 0.125f : 1.0f;
                __nv_bfloat16* outh = (region == 0) ? g_Qbh : g_Kbh;
                __nv_bfloat16* outl = (region == 0) ? g_Qbl : g_Kbl;
                size_t ob = (region == 0)
                    ? (size_t)row * E_ + colbase
                    : (size_t)row * KVW + (colbase - E_);
#pragma unroll
                for (int ni = 0; ni < 4; ni++) {
                    int d = ni * 8 + t2;             // 0..30
                    float a0  = acc[mi][ni][rr * 2];
                    float a0b = acc[mi][ni][rr * 2 + 1];
                    float a1  = acc[mi][ni + 4][rr * 2];
                    float a1b = acc[mi][ni + 4][rr * 2 + 1];
                    float2 cl = *(const float2*)&cosT[s * D_ + d];
                    float2 sl = *(const float2*)&sinT[s * D_ + d];
                    float2 ch = *(const float2*)&cosT[s * D_ + d + 32];
                    float2 sh = *(const float2*)&sinT[s * D_ + d + 32];
                    float r0  = (a0  * cl.x - a1  * sl.x) * scale;
                    float r0b = (a0b * cl.y - a1b * sl.y) * scale;
                    float r1  = (a1  * ch.x + a0  * sh.x) * scale;
                    float r1b = (a1b * ch.y + a0b * sh.y) * scale;
                    unsigned hi, lo;
                    split2(r0, r0b, hi, lo);
                    *(unsigned*)&outh[ob + d] = hi;
                    *(unsigned*)&outl[ob + d] = lo;
                    split2(r1, r1b, hi, lo);
                    *(unsigned*)&outh[ob + d + 32] = hi;
                    *(unsigned*)&outl[ob + d + 32] = lo;
                }
            }
        }
    }
}

// ---------------------------------------------------------------------------
// Tensor-core flash attention, split-bf16, Br=128, Bc=64, D=64.
// EXACTLY the R10 version (synchronous K/V loads, ldmatrix.x4 S-phase).
// ---------------------------------------------------------------------------
#define AST 72

__global__ __launch_bounds__(256) void attn_mma_kernel()
{
    extern __shared__ __nv_bfloat16 smb[];
    __nv_bfloat16* sQh = smb;
    __nv_bfloat16* sQl = smb + 128 * AST;
    __nv_bfloat16* sKh = smb + 256 * AST;
    __nv_bfloat16* sKl = smb + 320 * AST;
    __nv_bfloat16* sVh = smb + 384 * AST;
    __nv_bfloat16* sVl = smb + 448 * AST;

    int tid  = threadIdx.x;
    int lane = tid & 31;
    int wid  = tid >> 5;
    int g    = lane >> 2;
    int t2   = (lane & 3) * 2;
    int l16  = lane & 15;
    int lc8  = (lane >> 4) * 8;

    int qt = blockIdx.x, h = blockIdx.y, b = blockIdx.z;
    int kvh = h >> 2;
    int s0 = qt * 128;

    const __nv_bfloat16* Qhg = g_Qbh + ((size_t)(b * S_ + s0)) * E_ + h * D_;
    const __nv_bfloat16* Qlg = g_Qbl + ((size_t)(b * S_ + s0)) * E_ + h * D_;
    const __nv_bfloat16* Khg = g_Kbh + (size_t)b * S_ * KVW + kvh * D_;
    const __nv_bfloat16* Klg = g_Kbl + (size_t)b * S_ * KVW + kvh * D_;
    const __nv_bfloat16* Vhg = g_Vbh + (size_t)b * S_ * KVW + kvh * D_;
    const __nv_bfloat16* Vlg = g_Vbl + (size_t)b * S_ * KVW + kvh * D_;

    for (int c = tid; c < 1024; c += 256) {
        int r = c >> 3, col = (c & 7) * 8;
        *(uint4*)&sQh[r * AST + col] = *(const uint4*)&Qhg[(size_t)r * E_ + col];
        *(uint4*)&sQl[r * AST + col] = *(const uint4*)&Qlg[(size_t)r * E_ + col];
    }

    int wr = wid * 16;
    float m0r = -1e30f, m1r = -1e30f, l0r = 0.0f, l1r = 0.0f;
    float O[8][4];
#pragma unroll
    for (int nt = 0; nt < 8; nt++)
#pragma unroll
        for (int r = 0; r < 4; r++) O[nt][r] = 0.0f;

    for (int kt0 = 0; kt0 < S_ / 64; kt0++) {
        int t0 = kt0 * 64;
        for (int c = tid; c < 512; c += 256) {
            int r = c >> 3, col = (c & 7) * 8;
            size_t ga = (size_t)(t0 + r) * KVW + col;
            *(uint4*)&sKh[r * AST + col] = *(const uint4*)&Khg[ga];
            *(uint4*)&sKl[r * AST + col] = *(const uint4*)&Klg[ga];
            *(uint4*)&sVh[r * AST + col] = *(const uint4*)&Vhg[ga];
            *(uint4*)&sVl[r * AST + col] = *(const uint4*)&Vlg[ga];
        }
        __syncthreads();

        float acc[8][4];
#pragma unroll
        for (int nt = 0; nt < 8; nt++)
#pragma unroll
            for (int r = 0; r < 4; r++) acc[nt][r] = 0.0f;

#pragma unroll
        for (int kt = 0; kt < 4; kt++) {
            int col = kt * 16 + lc8;
            unsigned ah[4], al[4];
            ldmx4(ah, sQh + (wr + l16) * AST + col);
            ldmx4(al, sQl + (wr + l16) * AST + col);
#pragma unroll
            for (int nq = 0; nq < 4; nq++) {
                unsigned bh4[4], bl4[4];
                ldmx4(bh4, sKh + (nq * 16 + l16) * AST + col);
                ldmx4(bl4, sKl + (nq * 16 + l16) * AST + col);
                mma16816_b2(acc[2 * nq],     ah, bh4[0], bh4[2]);
                mma16816_b2(acc[2 * nq],     ah, bl4[0], bl4[2]);
                mma16816_b2(acc[2 * nq],     al, bh4[0], bh4[2]);
                mma16816_b2(acc[2 * nq + 1], ah, bh4[1], bh4[3]);
                mma16816_b2(acc[2 * nq + 1], ah, bl4[1], bl4[3]);
                mma16816_b2(acc[2 * nq + 1], al, bh4[1], bh4[3]);
            }
        }

        float mx0 = -1e30f, mx1 = -1e30f;
#pragma unroll
        for (int nt = 0; nt < 8; nt++) {
            mx0 = fmaxf(mx0, fmaxf(acc[nt][0], acc[nt][1]));
            mx1 = fmaxf(mx1, fmaxf(acc[nt][2], acc[nt][3]));
        }
        mx0 = fmaxf(mx0, __shfl_xor_sync(0xffffffffu, mx0, 1));
        mx0 = fmaxf(mx0, __shfl_xor_sync(0xffffffffu, mx0, 2));
        mx1 = fmaxf(mx1, __shfl_xor_sync(0xffffffffu, mx1, 1));
        mx1 = fmaxf(mx1, __shfl_xor_sync(0xffffffffu, mx1, 2));
        float nm0 = fmaxf(m0r, mx0), nm1 = fmaxf(m1r, mx1);
        float corr0 = __expf(m0r - nm0), corr1 = __expf(m1r - nm1);
        m0r = nm0; m1r = nm1;

        float sum0 = 0.0f, sum1 = 0.0f;
#pragma unroll
        for (int nt = 0; nt < 8; nt++) {
            acc[nt][0] = __expf(acc[nt][0] - nm0); sum0 += acc[nt][0];
            acc[nt][1] = __expf(acc[nt][1] - nm0); sum0 += acc[nt][1];
            acc[nt][2] = __expf(acc[nt][2] - nm1); sum1 += acc[nt][2];
            acc[nt][3] = __expf(acc[nt][3] - nm1); sum1 += acc[nt][3];
        }
        sum0 += __shfl_xor_sync(0xffffffffu, sum0, 1);
        sum0 += __shfl_xor_sync(0xffffffffu, sum0, 2);
        sum1 += __shfl_xor_sync(0xffffffffu, sum1, 1);
        sum1 += __shfl_xor_sync(0xffffffffu, sum1, 2);
        l0r = l0r * corr0 + sum0;
        l1r = l1r * corr1 + sum1;
#pragma unroll
        for (int nt = 0; nt < 8; nt++) {
            O[nt][0] *= corr0; O[nt][1] *= corr0;
            O[nt][2] *= corr1; O[nt][3] *= corr1;
        }

#pragma unroll
        for (int kt = 0; kt < 4; kt++) {
            unsigned ph[4], pl[4];
            split2(acc[2 * kt][0],     acc[2 * kt][1],     ph[0], pl[0]);
            split2(acc[2 * kt][2],     acc[2 * kt][3],     ph[1], pl[1]);
            split2(acc[2 * kt + 1][0], acc[2 * kt + 1][1], ph[2], pl[2]);
            split2(acc[2 * kt + 1][2], acc[2 * kt + 1][3], ph[3], pl[3]);
            const __nv_bfloat16* vh_base = sVh + (kt * 16 + l16) * AST;
            const __nv_bfloat16* vl_base = sVl + (kt * 16 + l16) * AST;
#pragma unroll
            for (int nt = 0; nt < 8; nt++) {
                unsigned bh[2], bl[2];
                ldmx2t(bh[0], bh[1], vh_base + nt * 8);
                ldmx2t(bl[0], bl[1], vl_base + nt * 8);
                mma16816(O[nt], ph, bh);
                mma16816(O[nt], ph, bl);
                mma16816(O[nt], pl, bh);
            }
        }
        __syncthreads();
    }

    float inv0 = 1.0f / l0r, inv1 = 1.0f / l1r;
    size_t row0 = (size_t)(b * S_ + s0 + wr + g) * E_ + h * D_;
    size_t row1 = (size_t)(b * S_ + s0 + wr + g + 8) * E_ + h * D_;
#pragma unroll
    for (int nt = 0; nt < 8; nt++) {
        unsigned hi, lo;
        split2(O[nt][0] * inv0, O[nt][1] * inv0, hi, lo);
        *(unsigned*)&g_attn_hi[row0 + nt * 8 + t2] = hi;
        *(unsigned*)&g_attn_lo[row0 + nt * 8 + t2] = lo;
        split2(O[nt][2] * inv1, O[nt][3] * inv1, hi, lo);
        *(unsigned*)&g_attn_hi[row1 + nt * 8 + t2] = hi;
        *(unsigned*)&g_attn_lo[row1 + nt * 8 + t2] = lo;
    }
}

// ---------------------------------------------------------------------------
// Launch
// ---------------------------------------------------------------------------
extern "C" void kernel_launch(void* const* d_in, const int* in_sizes, int n_in,
                              void* d_out, int out_size)
{
    const float* x    = (const float*)d_in[0];
    const float* cosT = (const float*)d_in[1];
    const float* sinT = (const float*)d_in[2];
    const float* Wq   = (const float*)d_in[3];
    const float* Wk   = (const float*)d_in[4];
    const float* Wv   = (const float*)d_in[5];
    const float* Wo   = (const float*)d_in[6];
    float* out = (float*)d_out;

    __nv_bfloat16 *xh, *xl, *wh, *wl, *oh, *ol, *ah, *al;
    cudaGetSymbolAddress((void**)&xh, g_x_hi);    cudaGetSymbolAddress((void**)&xl, g_x_lo);
    cudaGetSymbolAddress((void**)&wh, g_Wqkv_hi); cudaGetSymbolAddress((void**)&wl, g_Wqkv_lo);
    cudaGetSymbolAddress((void**)&oh, g_Wo_hi);   cudaGetSymbolAddress((void**)&ol, g_Wo_lo);
    cudaGetSymbolAddress((void**)&ah, g_attn_hi); cudaGetSymbolAddress((void**)&al, g_attn_lo);

    const int M = B_ * S_;   // 4096

    cudaFuncSetAttribute(gemm_split_nt3_kernel<0>,
                         cudaFuncAttributeMaxDynamicSharedMemorySize, GEMM_SMEM);
    cudaFuncSetAttribute(gemm_split_nt3_kernel<1>,
                         cudaFuncAttributeMaxDynamicSharedMemorySize, GEMM_SMEM);
    cudaFuncSetAttribute(attn_mma_kernel,
                         cudaFuncAttributeMaxDynamicSharedMemorySize,
                         512 * AST * (int)sizeof(__nv_bfloat16));

    // Split conversions: x + weights (Wq/Wk/Wv fused rows, Wo)
    {
        int nx = M * E_;
        split_kernel<<<(nx + 255) / 256, 256>>>(x, xh, xl, nx);
        int nq = E_ * E_;
        int nk = KVW * E_;
        split_kernel<<<(nq + 255) / 256, 256>>>(Wq, wh, wl, nq);
        split_kernel<<<(nk + 255) / 256, 256>>>(Wk, wh + (size_t)E_ * E_,
                                                wl + (size_t)E_ * E_, nk);
        split_kernel<<<(nk + 255) / 256, 256>>>(Wv, wh + (size_t)(E_ + KVW) * E_,
                                                wl + (size_t)(E_ + KVW) * E_, nk);
        split_kernel<<<(nq + 255) / 256, 256>>>(Wo, oh, ol, nq);
    }

    // Fused QKV projection with rope+scale+split epilogue (MODE 1)
    gemm_split_nt3_kernel<1><<<dim3(NQKV / 256, M / 128), 256, GEMM_SMEM>>>(
        xh, xl, wh, wl, nullptr, M, NQKV, E_, cosT, sinT);

    // Attention (R10 version)
    attn_mma_kernel<<<dim3(S_ / 128, H_, B_), 256,
                      512 * AST * sizeof(__nv_bfloat16)>>>();

    // Output projection -> d_out (MODE 0)
    gemm_split_nt3_kernel<0><<<dim3(E_ / 256, M / 128), 256, GEMM_SMEM>>>(
        ah, al, oh, ol, out, M, E_, E_, nullptr, nullptr);
}